// round 5
// baseline (speedup 1.0000x reference)
#include <cuda_runtime.h>
#include <cuda_bf16.h>

constexpr int B  = 8;
constexpr int T  = 256;
constexpr int U  = 64;
constexpr int U1 = U + 1;                 // 65
constexpr int V  = 1024;
constexpr int ROWS_PER_T = B * U1;        // 520
constexpr int BLKS_PER_T = ROWS_PER_T/8;  // 65 softmax blocks per frame
constexpr int NSBLK = B * T * U1 / 8;     // 16640 softmax blocks
constexpr int PAD = 128;                  // stream over/under-run guard

#define NEGV (-1e30f)

// Scratch (allocation-free rule: __device__ globals).
// blank[b][u][t] then emit[b][u][t], padded both ends for streaming overrun.
__device__ float g_scratch[2*PAD + B*U1*T + B*U*T];
__device__ float g_ll[B];
__device__ int   g_cnt[T];    // completed softmax blocks per frame (target 65)
__device__ int   g_done;      // completed alpha warps

__device__ __forceinline__ float ladd(float x, float y)
{
    float m = fmaxf(x, y);
    return m + __logf(1.0f + __expf(-fabsf(x - y)));
}
__device__ __forceinline__ void pf_l1(const float* p)
{
    asm volatile("prefetch.global.L1 [%0];" :: "l"(p));
}

// ---------------------------------------------------------------------------
// Fused kernel.
//   blockIdx 0..7      : alpha wavefront for batch b (one warp), chasing.
//   blockIdx 8..16647  : softmax blocks, 8 rows each, t-major global order.
// ---------------------------------------------------------------------------
__global__ void __launch_bounds__(256, 6) rnnt_fused(
    const float* __restrict__ logits,
    const int*   __restrict__ labels,
    const int*   __restrict__ f_len,
    const int*   __restrict__ y_len,
    float*       __restrict__ out)
{
    float* blank = g_scratch + PAD;
    float* emit  = g_scratch + PAD + B*U1*T;

    if (blockIdx.x >= B) {
        // ================= softmax path =================
        int gw   = (blockIdx.x - B) * 8 + (threadIdx.x >> 5);
        int lane = threadIdx.x & 31;
        int t    = gw / ROWS_PER_T;            // t-major global order
        int rem  = gw - t * ROWS_PER_T;
        int b    = rem / U1;
        int u    = rem - b * U1;
        size_t rowoff = ((size_t)(b * T + t) * U1 + u);
        const float4* row = reinterpret_cast<const float4*>(logits) + rowoff * (V/4);

        float4 v[8];
        float mx = -3.4e38f;
#pragma unroll
        for (int k = 0; k < 8; k++) {
            v[k] = row[k * 32 + lane];
            mx = fmaxf(mx, fmaxf(fmaxf(v[k].x, v[k].y), fmaxf(v[k].z, v[k].w)));
        }
#pragma unroll
        for (int o = 16; o; o >>= 1) mx = fmaxf(mx, __shfl_xor_sync(0xffffffffu, mx, o));
        float s = 0.f;
#pragma unroll
        for (int k = 0; k < 8; k++) {
            s += __expf(v[k].x - mx) + __expf(v[k].y - mx)
               + __expf(v[k].z - mx) + __expf(v[k].w - mx);
        }
#pragma unroll
        for (int o = 16; o; o >>= 1) s += __shfl_xor_sync(0xffffffffu, s, o);
        float lse = mx + __logf(s);

        if (lane == 0) {
            blank[(b * U1 + u) * T + t] = v[0].x - lse;
            if (u < U) {
                float e = NEGV;
                if (u < y_len[b]) {
                    int l = labels[b * U + u];
                    e = __ldg(logits + rowoff * V + l) - lse;   // L1 hit
                }
                emit[(b * U + u) * T + t] = e;
            }
            __threadfence();                    // release writer's stores
        }
        __syncthreads();
        if (threadIdx.x == 0) atomicAdd(&g_cnt[t], 1);
        return;
    }

    // ================= alpha path (one warp per batch) =================
    if (threadIdx.x >= 32) return;
    int lane = threadIdx.x;
    int b    = blockIdx.x;
    int tl   = f_len[b] - 1;                    // last valid frame
    int yl   = y_len[b];                        // label length
    const int dmax = tl + yl;

    const float* blank_b = blank + b * U1 * T;
    const float* emit_b  = emit  + b * U  * T;

    const int uA = 2 * lane, uB = 2 * lane + 1;
    // Streams indexed by diagonal d (advance +1 float per diagonal):
    const float* pA = blank_b + uA * (T - 1) - 1;            // blank[uA][d-uA-1]
    const float* pB = blank_b + uB * (T - 1) - 1;
    const float* pC = blank_b + 64 * (T - 1) - 1;
    const float* qA = (uA == 0) ? emit_b : emit_b + (uA-1)*T - uA;  // emit[uA-1][d-uA]
    const float* qB = emit_b + (uB - 1) * T - uB;
    const float* qC = emit_b + 63 * T - 64;

    int w = 0;   // frames [0, w) known complete
    auto WAIT = [&](int F) {
        if (lane == 0) {
            int guard = 0;
            while (w <= F && guard < (1 << 27)) {
                if (*(volatile int*)&g_cnt[w] == BLKS_PER_T) w++;
                else { __nanosleep(128); guard++; }
            }
        }
        w = __shfl_sync(0xffffffffu, w, 0);
        __threadfence();                        // acquire for all lanes
    };

    WAIT(min(95, tl));                          // covers chunk 0 incl. line spans

    // alpha[0][u] = exclusive cumsum of emit[0][*] (warp scan on pairs)
    float e0A = __ldg(emit_b + uA * T);
    float e0B = __ldg(emit_b + uB * T);
    float S = e0A + e0B;
#pragma unroll
    for (int o = 1; o < 32; o <<= 1) {
        float tv = __shfl_up_sync(0xffffffffu, S, o);
        if (lane >= o) S += tv;
    }
    float Sx = __shfl_up_sync(0xffffffffu, S, 1);
    if (lane == 0) Sx = 0.f;
    float a0A = Sx;
    float a0B = Sx + e0A;
    float a0C = __shfl_sync(0xffffffffu, S, 31);

    float aA = NEGV, aB = NEGV, aC = NEGV, ll = 0.f;

    for (int dc = 0; dc < 320; dc += 32) {
        if (dc) WAIT(min(dc + 95, tl));         // lookahead covers prefetch lines
        pf_l1(pA + dc + 32); pf_l1(pA + dc + 63);
        pf_l1(pB + dc + 32); pf_l1(pB + dc + 63);
        pf_l1(pC + dc + 32); pf_l1(pC + dc + 63);
        pf_l1(qA + dc + 32); pf_l1(qA + dc + 63);
        pf_l1(qB + dc + 32); pf_l1(qB + dc + 63);
        pf_l1(qC + dc + 32); pf_l1(qC + dc + 63);
#pragma unroll 8
        for (int s = 0; s < 32; s++) {
            int d = dc + s;
            float oA = aA, oB = aB, oC = aC;
            float pm1 = __shfl_up_sync(0xffffffffu, oB, 1);   // prev[2l-1]

            float sbA = __ldg(pA + d);
            float sbB = __ldg(pB + d);
            float sbC = __ldg(pC + d);
            float seA = (uA == 0) ? NEGV : __ldg(qA + d);
            float seB = __ldg(qB + d);
            float seC = __ldg(qC + d);

            float nA = ladd(oA + sbA, pm1 + seA);
            float nB = ladd(oB + sbB, oA  + seB);
            float nC = ladd(oC + sbC, oB  + seC);

            nA = (d == uA) ? a0A : nA;          // t==0 init
            nB = (d == uB) ? a0B : nB;
            nC = (d == 64) ? a0C : nC;
            aA = (d < uA) ? oA : nA;            // inactive: hold
            aB = (d < uB) ? oB : nB;
            aC = (d < 64) ? oC : nC;

            if (d == dmax) {                    // capture alpha[tl][yl]
                if (uA == yl)                    ll = nA;
                else if (uB == yl)               ll = nB;
                else if (lane == 31 && yl == 64) ll = nC;
            }
        }
    }

    bool hit = (uA == yl) || (uB == yl) || (lane == 31 && yl == 64);
    if (hit) g_ll[b] = ll + __ldg(blank_b + yl * T + tl);
    __syncwarp();
    __threadfence();
    if (lane == 0) atomicAdd(&g_done, 1);

    // Block 0 lane 0: final reduction + counter reset for next graph replay.
    if (b == 0 && lane == 0) {
        int guard = 0;
        while (*(volatile int*)&g_done < B && guard < (1 << 27)) {
            __nanosleep(128); guard++;
        }
        __threadfence();
        float sum = 0.f;
        for (int i = 0; i < B; i++) sum += g_ll[i];
        out[0] = -sum * (1.0f / B);
        for (int t2 = 0; t2 < T; t2++) {        // all softmax blocks done?
            guard = 0;
            while (*(volatile int*)&g_cnt[t2] != BLKS_PER_T && guard < (1 << 27)) {
                __nanosleep(128); guard++;
            }
        }
        for (int t2 = 0; t2 < T; t2++) g_cnt[t2] = 0;
        g_done = 0;
    }
}

// ---------------------------------------------------------------------------
extern "C" void kernel_launch(void* const* d_in, const int* in_sizes, int n_in,
                              void* d_out, int out_size)
{
    const float* logits = (const float*)d_in[0];
    const int*   labels = (const int*)  d_in[1];
    const int*   f_len  = (const int*)  d_in[2];
    const int*   y_len  = (const int*)  d_in[3];

    rnnt_fused<<<NSBLK + B, 256>>>(logits, labels, f_len, y_len, (float*)d_out);
}

// round 6
// speedup vs baseline: 2.0147x; 2.0147x over previous
#include <cuda_runtime.h>
#include <cuda_bf16.h>

constexpr int B  = 8;
constexpr int T  = 256;
constexpr int U  = 64;
constexpr int U1 = U + 1;   // 65
constexpr int V  = 1024;
constexpr int PAD = 32;     // front pad: alpha streams read index -1

#define NEGV (-1e30f)
#define INV_LN2 1.4426950408889634f
#define LN2     0.6931471805599453f

// Scratch (allocation-free rule: __device__ globals).
// log2-domain log-probs, TRANSPOSED [b][u][t] so alpha streams advance +1 in t.
__device__ float g_scratch[PAD + B * U1 * T + B * U * T];

// ---------------------------------------------------------------------------
// Kernel 1: one warp per (b,t,u) row of V=1024. Register-resident row
// (8 x float4 per lane), warp max + warp sum-exp. HBM-bound: 545 MB read.
// Emits blank/emit scaled by 1/ln2 (log2 domain) for the alpha recurrence.
// ---------------------------------------------------------------------------
__global__ void __launch_bounds__(256) softmax_kernel(
    const float* __restrict__ logits,
    const int*   __restrict__ labels,
    const int*   __restrict__ y_len)
{
    int gw   = (blockIdx.x * blockDim.x + threadIdx.x) >> 5;   // global warp = row
    int lane = threadIdx.x & 31;
    if (gw >= B * T * U1) return;

    const float4* row = reinterpret_cast<const float4*>(logits) + (size_t)gw * (V / 4);

    float4 v[8];
    float mx = -3.4e38f;
#pragma unroll
    for (int k = 0; k < 8; k++) {
        v[k] = row[k * 32 + lane];                       // coalesced 128B/warp
        mx = fmaxf(mx, fmaxf(fmaxf(v[k].x, v[k].y), fmaxf(v[k].z, v[k].w)));
    }
#pragma unroll
    for (int o = 16; o; o >>= 1) mx = fmaxf(mx, __shfl_xor_sync(0xffffffffu, mx, o));

    float s = 0.f;
#pragma unroll
    for (int k = 0; k < 8; k++) {
        s += __expf(v[k].x - mx) + __expf(v[k].y - mx)
           + __expf(v[k].z - mx) + __expf(v[k].w - mx);
    }
#pragma unroll
    for (int o = 16; o; o >>= 1) s += __shfl_xor_sync(0xffffffffu, s, o);

    float lse = mx + __logf(s);

    if (lane == 0) {
        float* blank = g_scratch + PAD;
        float* emit  = g_scratch + PAD + B * U1 * T;
        int b = gw / (T * U1);
        int r = gw % (T * U1);
        int t = r / U1;
        int u = r % U1;
        blank[(b * U1 + u) * T + t] = (v[0].x - lse) * INV_LN2;
        if (u < U) {
            float e = NEGV;
            if (u < y_len[b]) {
                int l = labels[b * U + u];
                e = (__ldg(logits + (size_t)gw * V + l) - lse) * INV_LN2;  // L1 hit
            }
            emit[(b * U + u) * T + t] = e;
        }
    }
}

// ---------------------------------------------------------------------------
// Kernel 2: alpha recurrence + final reduction, ONE block, 8 warps.
// Warp b handles batch b: lane l owns u = {2l, 2l+1}; lane 31 also u = 64.
// Per diagonal: one __shfl_up, register-resident state, streams read straight
// from L2 via __ldg (addresses independent of alpha -> off the serial chain).
//
//   alpha[t][u] = ladd2(alpha[t-1][u] + blank[t-1][u],
//                       alpha[t][u-1] + emit[t][u-1])      (log2 domain)
//   alpha[0][u] = cumsum(emit[0][0..u-1])
// ---------------------------------------------------------------------------
__device__ __forceinline__ float ladd2(float x, float y)
{
    float m = fmaxf(x, y);
    return m + __log2f(1.0f + exp2f(-fabsf(x - y)));   // bare MUFU chain
}

__global__ void __launch_bounds__(256) alpha_kernel(
    const int* __restrict__ f_len,
    const int* __restrict__ y_len,
    float*     __restrict__ out)
{
    __shared__ float sll[B];

    int lane = threadIdx.x & 31;
    int b    = threadIdx.x >> 5;           // warp = batch, 8 warps

    const float* blank_b = g_scratch + PAD + b * U1 * T;
    const float* emit_b  = g_scratch + PAD + B * U1 * T + b * U * T;

    int tl = __ldg(f_len + b) - 1;         // last valid frame (127..255)
    int yl = __ldg(y_len + b);             // label length    (32..64)
    const int dmax = tl + yl;

    const int uA = 2 * lane, uB = 2 * lane + 1;
    // Streams indexed by diagonal d (advance +1 float per diagonal):
    const float* pA = blank_b + uA * (T - 1) - 1;                   // blank[uA][d-uA-1]
    const float* pB = blank_b + uB * (T - 1) - 1;
    const float* pC = blank_b + 64 * (T - 1) - 1;
    const float* qA = (uA == 0) ? emit_b : emit_b + (uA - 1) * T - uA;  // emit[uA-1][d-uA]
    const float* qB = emit_b + (uB - 1) * T - uB;
    const float* qC = emit_b + 63 * T - 64;

    // alpha[0][u] = exclusive cumsum of emit[0][*] (warp scan on pairs)
    float e0A = __ldg(emit_b + uA * T);
    float e0B = __ldg(emit_b + uB * T);
    float S = e0A + e0B;
#pragma unroll
    for (int o = 1; o < 32; o <<= 1) {
        float tv = __shfl_up_sync(0xffffffffu, S, o);
        if (lane >= o) S += tv;
    }
    float Sx = __shfl_up_sync(0xffffffffu, S, 1);
    if (lane == 0) Sx = 0.f;
    float a0A = Sx;
    float a0B = Sx + e0A;
    float a0C = __shfl_sync(0xffffffffu, S, 31);

    float aA = NEGV, aB = NEGV, aC = NEGV, ll = 0.f;

#pragma unroll 8
    for (int d = 0; d < 320; d++) {
        float oA = aA, oB = aB, oC = aC;
        float pm1 = __shfl_up_sync(0xffffffffu, oB, 1);    // prev[2l-1]

        float sbA = __ldg(pA + d);
        float sbB = __ldg(pB + d);
        float sbC = __ldg(pC + d);
        float seA = (uA == 0) ? NEGV : __ldg(qA + d);
        float seB = __ldg(qB + d);
        float seC = __ldg(qC + d);

        float nA = ladd2(oA + sbA, pm1 + seA);
        float nB = ladd2(oB + sbB, oA  + seB);
        float nC = ladd2(oC + sbC, oB  + seC);

        nA = (d == uA) ? a0A : nA;            // t==0 init row
        nB = (d == uB) ? a0B : nB;
        nC = (d == 64) ? a0C : nC;
        aA = (d < uA) ? oA : nA;              // inactive: hold
        aB = (d < uB) ? oB : nB;
        aC = (d < 64) ? oC : nC;

        if (d == dmax) {                      // capture alpha[tl][yl]
            if (uA == yl)                    ll = nA;
            else if (uB == yl)               ll = nB;
            else if (lane == 31 && yl == 64) ll = nC;
        }
    }

    bool hit = (uA == yl) || (uB == yl) || (lane == 31 && yl == 64);
    if (hit) sll[b] = ll + __ldg(blank_b + yl * T + tl);
    __syncthreads();

    if (threadIdx.x == 0) {
        float sum = 0.f;
#pragma unroll
        for (int i = 0; i < B; i++) sum += sll[i];
        out[0] = -sum * (LN2 / B);            // back to natural log, mean
    }
}

// ---------------------------------------------------------------------------
extern "C" void kernel_launch(void* const* d_in, const int* in_sizes, int n_in,
                              void* d_out, int out_size)
{
    const float* logits = (const float*)d_in[0];
    const int*   labels = (const int*)  d_in[1];
    const int*   f_len  = (const int*)  d_in[2];
    const int*   y_len  = (const int*)  d_in[3];

    int rows = B * T * U1;                    // 133,120 warps
    int blocks = (rows * 32 + 255) / 256;
    softmax_kernel<<<blocks, 256>>>(logits, labels, y_len);

    alpha_kernel<<<1, 256>>>(f_len, y_len, (float*)d_out);
}

// round 8
// speedup vs baseline: 3.4490x; 1.7120x over previous
#include <cuda_runtime.h>
#include <cuda_bf16.h>

constexpr int B  = 8;
constexpr int T  = 256;
constexpr int U  = 64;
constexpr int U1 = U + 1;   // 65
constexpr int V  = 1024;

#define NEGV (-1e30f)
#define INV_LN2 1.4426950408889634f
#define LN2     0.6931471805599453f

// Scratch (allocation-free rule: __device__ globals).
// log2-domain log-probs, TRANSPOSED [b][u][t] so alpha streams advance +1 in t.
__device__ float g_blank[B * U1 * T];
__device__ float g_emit [B * U  * T];
__device__ float g_ll   [B];
__device__ int   g_done;          // alpha blocks finished (last one reduces)

// ---------------------------------------------------------------------------
// Kernel 1: one warp per (b,t,u) row of V=1024. Register-resident row
// (8 x float4 per lane), warp max + warp sum-exp. HBM-bound: 545 MB read.
// Emits blank/emit scaled by 1/ln2 (log2 domain) for the alpha recurrence.
// ---------------------------------------------------------------------------
__global__ void __launch_bounds__(256) softmax_kernel(
    const float* __restrict__ logits,
    const int*   __restrict__ labels,
    const int*   __restrict__ y_len)
{
    int gw   = (blockIdx.x * blockDim.x + threadIdx.x) >> 5;   // global warp = row
    int lane = threadIdx.x & 31;
    if (gw >= B * T * U1) return;

    const float4* row = reinterpret_cast<const float4*>(logits) + (size_t)gw * (V / 4);

    float4 v[8];
    float mx = -3.4e38f;
#pragma unroll
    for (int k = 0; k < 8; k++) {
        v[k] = row[k * 32 + lane];                       // coalesced 128B/warp
        mx = fmaxf(mx, fmaxf(fmaxf(v[k].x, v[k].y), fmaxf(v[k].z, v[k].w)));
    }
#pragma unroll
    for (int o = 16; o; o >>= 1) mx = fmaxf(mx, __shfl_xor_sync(0xffffffffu, mx, o));

    float s = 0.f;
#pragma unroll
    for (int k = 0; k < 8; k++) {
        s += __expf(v[k].x - mx) + __expf(v[k].y - mx)
           + __expf(v[k].z - mx) + __expf(v[k].w - mx);
    }
#pragma unroll
    for (int o = 16; o; o >>= 1) s += __shfl_xor_sync(0xffffffffu, s, o);

    float lse = mx + __logf(s);

    if (lane == 0) {
        int b = gw / (T * U1);
        int r = gw % (T * U1);
        int t = r / U1;
        int u = r % U1;
        g_blank[(b * U1 + u) * T + t] = (v[0].x - lse) * INV_LN2;
        if (u < U) {
            float e = NEGV;
            if (u < y_len[b]) {
                int l = labels[b * U + u];
                e = (__ldg(logits + (size_t)gw * V + l) - lse) * INV_LN2;  // L1 hit
            }
            g_emit[(b * U + u) * T + t] = e;
        }
    }
}

// ---------------------------------------------------------------------------
// Kernel 2: alpha recurrence, one block per batch, warp-synchronous wavefront.
// 256 threads stage blank/emit into smem (133 KB), then warp 0 runs the
// diagonal recurrence with lane l owning u = {2l, 2l+1} (lane 31 also u=64):
// one __shfl_up per diagonal, zero __syncthreads in the loop, LDS reads
// (addresses alpha-independent -> hidden under the ~50-cyc ladd2 chain).
// Last block to finish reduces g_ll -> out and resets the ticket counter.
// ---------------------------------------------------------------------------
__device__ __forceinline__ float ladd2(float x, float y)
{
    float m = fmaxf(x, y);
    return m + __log2f(1.0f + exp2f(-fabsf(x - y)));   // bare MUFU chain
}

extern __shared__ float sh[];

__global__ void __launch_bounds__(256) alpha_kernel(
    const int* __restrict__ f_len,
    const int* __restrict__ y_len,
    float*     __restrict__ out)
{
    float* sb = sh;            // [U1][T] blank (log2 domain)
    float* se = sh + U1 * T;   // [U][T]  emit

    int b   = blockIdx.x;
    int tid = threadIdx.x;

    // Stage both arrays into smem (coalesced float4, from hot L2).
    {
        const float4* srcb = reinterpret_cast<const float4*>(g_blank + b * U1 * T);
        float4*       dstb = reinterpret_cast<float4*>(sb);
        for (int i = tid; i < U1 * T / 4; i += 256) dstb[i] = srcb[i];
        const float4* srce = reinterpret_cast<const float4*>(g_emit + b * U * T);
        float4*       dste = reinterpret_cast<float4*>(se);
        for (int i = tid; i < U * T / 4; i += 256) dste[i] = srce[i];
    }
    __syncthreads();
    if (tid >= 32) return;

    int lane = tid;
    int tl = __ldg(f_len + b) - 1;     // last valid frame (127..255)
    int yl = __ldg(y_len + b);         // label length    (32..64)
    const int dmax = tl + yl;

    const int uA = 2 * lane, uB = 2 * lane + 1;
    // Streams indexed by diagonal d (advance +1 float per diagonal):
    float* pA = sb + uA * (T - 1) - 1;                    // blank[uA][d-uA-1]
    float* pB = sb + uB * (T - 1) - 1;
    float* pC = sb + 64 * (T - 1) - 1;
    float* qA = (uA == 0) ? se : se + (uA - 1) * T - uA;  // emit[uA-1][d-uA]
    float* qB = se + (uB - 1) * T - uB;
    float* qC = se + 63 * T - 64;

    // alpha[0][u] = exclusive cumsum of emit[0][*] (warp scan on pairs)
    float e0A = se[uA * T];
    float e0B = se[uB * T];
    float S = e0A + e0B;
#pragma unroll
    for (int o = 1; o < 32; o <<= 1) {
        float tv = __shfl_up_sync(0xffffffffu, S, o);
        if (lane >= o) S += tv;
    }
    float Sx = __shfl_up_sync(0xffffffffu, S, 1);
    if (lane == 0) Sx = 0.f;
    float a0A = Sx;
    float a0B = Sx + e0A;
    float a0C = __shfl_sync(0xffffffffu, S, 31);

    float aA = NEGV, aB = NEGV, aC = NEGV, ll = 0.f;

#pragma unroll 8
    for (int d = 0; d < 320; d++) {
        float oA = aA, oB = aB, oC = aC;
        float pm1 = __shfl_up_sync(0xffffffffu, oB, 1);    // prev[2l-1]

        // lane0 d=0 reads pA[-1] = sb[-2]: clamp that single case in-range
        float sbA = pA[(d == 0 && lane == 0) ? 1 : d];
        float sbB = pB[d];
        float sbC = pC[d];
        float seA = (uA == 0) ? NEGV : qA[d];
        float seB = qB[d];
        float seC = qC[d];

        float nA = ladd2(oA + sbA, pm1 + seA);
        float nB = ladd2(oB + sbB, oA  + seB);
        float nC = ladd2(oC + sbC, oB  + seC);

        nA = (d == uA) ? a0A : nA;            // t==0 init row
        nB = (d == uB) ? a0B : nB;
        nC = (d == 64) ? a0C : nC;
        aA = (d < uA) ? oA : nA;              // inactive: hold
        aB = (d < uB) ? oB : nB;
        aC = (d < 64) ? oC : nC;

        if (d == dmax) {                      // capture alpha[tl][yl]
            if (uA == yl)                    ll = nA;
            else if (uB == yl)               ll = nB;
            else if (lane == 31 && yl == 64) ll = nC;
        }
    }

    bool hit = (uA == yl) || (uB == yl) || (lane == 31 && yl == 64);
    if (hit) g_ll[b] = ll + sb[yl * T + tl];
    __syncwarp();
    __threadfence();

    if (lane == 0) {
        int ticket = atomicAdd(&g_done, 1);
        if (ticket == B - 1) {                // last block: reduce + reset
            __threadfence();
            float sum = 0.f;
#pragma unroll
            for (int i = 0; i < B; i++) sum += g_ll[i];
            out[0] = -sum * (LN2 / B);        // back to natural log, mean
            g_done = 0;                       // deterministic across replays
        }
    }
}

// ---------------------------------------------------------------------------
extern "C" void kernel_launch(void* const* d_in, const int* in_sizes, int n_in,
                              void* d_out, int out_size)
{
    const float* logits = (const float*)d_in[0];
    const int*   labels = (const int*)  d_in[1];
    const int*   f_len  = (const int*)  d_in[2];
    const int*   y_len  = (const int*)  d_in[3];

    int rows = B * T * U1;                    // 133,120 warps
    int blocks = (rows * 32 + 255) / 256;
    softmax_kernel<<<blocks, 256>>>(logits, labels, y_len);

    size_t smem = (size_t)(U1 * T + U * T) * sizeof(float);   // 132,096 B
    cudaFuncSetAttribute(alpha_kernel,
                         cudaFuncAttributeMaxDynamicSharedMemorySize, (int)smem);
    alpha_kernel<<<B, 256, smem>>>(f_len, y_len, (float*)d_out);
}

// round 9
// speedup vs baseline: 3.9997x; 1.1597x over previous
#include <cuda_runtime.h>
#include <cuda_bf16.h>

constexpr int B  = 8;
constexpr int T  = 256;
constexpr int U  = 64;
constexpr int U1 = U + 1;   // 65
constexpr int V  = 1024;
constexpr int PKROW = 256;                // pk row stride (t dimension)
constexpr int PKSZ  = U1 * PKROW;         // 16640 float2 per batch
constexpr int PKPAD = 8;                  // prefetch overrun guard

#define NEGV (-1e30f)
#define INV_LN2 1.4426950408889634f
#define LN2     0.6931471805599453f

// Scratch (allocation-free rule: __device__ globals).
// Packed log2-domain operands: pk[b][u][t] = (blank[u][t-1], emit[u-1][t]).
// Cell u at diagonal d (t = d-u) reads exactly pk[u][t] -> one LDS.64.
__device__ float2 g_pack[B * PKSZ];
__device__ float  g_blast[B * U1];        // blank[u][t_last] for the final add
__device__ float  g_ll[B];
__device__ int    g_done;                 // ticket: last alpha block reduces

// ---------------------------------------------------------------------------
// Kernel 1: one warp per (b,t,u) row of V=1024. Register-resident row
// (8 x float4 per lane), warp max + warp sum-exp. HBM-bound: 545 MB read.
// Writes packed log2-domain operands for the alpha recurrence.
// ---------------------------------------------------------------------------
__global__ void __launch_bounds__(256) softmax_kernel(
    const float* __restrict__ logits,
    const int*   __restrict__ labels,
    const int*   __restrict__ f_len,
    const int*   __restrict__ y_len)
{
    int gw   = (blockIdx.x * blockDim.x + threadIdx.x) >> 5;   // global warp = row
    int lane = threadIdx.x & 31;
    if (gw >= B * T * U1) return;

    const float4* row = reinterpret_cast<const float4*>(logits) + (size_t)gw * (V / 4);

    float4 v[8];
    float mx = -3.4e38f;
#pragma unroll
    for (int k = 0; k < 8; k++) {
        v[k] = row[k * 32 + lane];                       // coalesced 128B/warp
        mx = fmaxf(mx, fmaxf(fmaxf(v[k].x, v[k].y), fmaxf(v[k].z, v[k].w)));
    }
#pragma unroll
    for (int o = 16; o; o >>= 1) mx = fmaxf(mx, __shfl_xor_sync(0xffffffffu, mx, o));

    float s = 0.f;
#pragma unroll
    for (int k = 0; k < 8; k++) {
        s += __expf(v[k].x - mx) + __expf(v[k].y - mx)
           + __expf(v[k].z - mx) + __expf(v[k].w - mx);
    }
#pragma unroll
    for (int o = 16; o; o >>= 1) s += __shfl_xor_sync(0xffffffffu, s, o);

    float lse = mx + __logf(s);

    if (lane == 0) {
        int b = gw / (T * U1);
        int r = gw % (T * U1);
        int t = r / U1;
        int u = r % U1;
        float* pk = reinterpret_cast<float*>(g_pack + b * PKSZ);
        float bl = (v[0].x - lse) * INV_LN2;
        if (t + 1 < PKROW) pk[(u * PKROW + t + 1) * 2 + 0] = bl;   // .x slot
        if (t == f_len[b] - 1) g_blast[b * U1 + u] = bl;
        if (u < U) {
            float e = NEGV;
            if (u < y_len[b]) {
                int l = labels[b * U + u];
                e = (__ldg(logits + (size_t)gw * V + l) - lse) * INV_LN2;  // L1 hit
            }
            pk[((u + 1) * PKROW + t) * 2 + 1] = e;                 // .y slot
        }
    }
}

// ---------------------------------------------------------------------------
// Kernel 2: alpha recurrence, one block per batch. 256 threads stage the
// packed operand array (133 KB) into smem, then warp 0 runs the diagonal
// wavefront: lane l owns u = {2l, 2l+1}; all lanes also compute u = 64
// (broadcast smem read; only lane 31's value is used).
// Ramp phase d in [0,64] carries init/hold selects; steady phase d in
// [65, dmax] is the bare recurrence with software-pipelined LDS.64 loads.
// alpha[tl][yl] is the owning lane's register at loop exit (d stops at dmax).
// Last block to finish reduces g_ll -> out (ticket) and resets the counter.
// ---------------------------------------------------------------------------
__device__ __forceinline__ float ladd2(float x, float y)
{
    float m = fmaxf(x, y);
    return m + __log2f(1.0f + exp2f(-fabsf(x - y)));   // bare MUFU chain
}

extern __shared__ float2 shpk[];           // [PKSZ + PKPAD]

__global__ void __launch_bounds__(256) alpha_kernel(
    const int* __restrict__ f_len,
    const int* __restrict__ y_len,
    float*     __restrict__ out)
{
    int b   = blockIdx.x;
    int tid = threadIdx.x;

    // Stage packed operands into smem (coalesced float4, from hot L2).
    {
        const float4* src = reinterpret_cast<const float4*>(g_pack + b * PKSZ);
        float4*       dst = reinterpret_cast<float4*>(shpk);
        for (int i = tid; i < PKSZ / 2; i += 256) dst[i] = src[i];
    }
    __syncthreads();
    if (tid >= 32) return;

    int lane = tid;
    int tl = __ldg(f_len + b) - 1;         // last valid frame (127..255)
    int yl = __ldg(y_len + b);             // label length    (32..64)
    const int dmax = tl + yl;              // >= 159 always

    const int uA = 2 * lane, uB = 2 * lane + 1;
    // Stream for cell u, indexed by diagonal d: shpk[u*(PKROW-1) + d]
    const float2* sA = shpk + uA * (PKROW - 1);
    const float2* sB = shpk + uB * (PKROW - 1);
    const float2* sC = shpk + 64 * (PKROW - 1);     // same addr all lanes: bcast

    // alpha[0][u] = exclusive cumsum of emit[0][*]  (emit[0][u] = pk[u+1][0].y)
    float e0A = shpk[(uA + 1) * PKROW].y;
    float e0B = shpk[(uB + 1) * PKROW].y;
    float S = e0A + e0B;
#pragma unroll
    for (int o = 1; o < 32; o <<= 1) {
        float tv = __shfl_up_sync(0xffffffffu, S, o);
        if (lane >= o) S += tv;
    }
    float Sx = __shfl_up_sync(0xffffffffu, S, 1);
    if (lane == 0) Sx = 0.f;
    float a0A = Sx;
    float a0B = Sx + e0A;
    float a0C = __shfl_sync(0xffffffffu, S, 31);

    float aA = NEGV, aB = NEGV, aC = NEGV;

    // ---- ramp phase: d in [0, 64], full init/hold predication ----
#pragma unroll 4
    for (int d = 0; d <= 64; d++) {
        float oA = aA, oB = aB, oC = aC;
        float pm1 = __shfl_up_sync(0xffffffffu, oB, 1);    // prev[2l-1]

        float2 wA = sA[d];
        float2 wB = sB[d];
        float2 wC = sC[d];
        float seA = (lane == 0) ? NEGV : wA.y;             // emit[-1] = NEG

        float nA = ladd2(oA + wA.x, pm1 + seA);
        float nB = ladd2(oB + wB.x, oA  + wB.y);
        float nC = ladd2(oC + wC.x, oB  + wC.y);

        nA = (d == uA) ? a0A : nA;            // t==0 init row
        nB = (d == uB) ? a0B : nB;
        nC = (d == 64) ? a0C : nC;
        aA = (d < uA) ? oA : nA;              // inactive: hold
        aB = (d < uB) ? oB : nB;
        aC = nC;                              // uC=64: held until d==64 init
    }

    // ---- steady phase: d in [65, dmax], bare recurrence, pipelined loads ----
    float2 wA = sA[65], wB = sB[65], wC = sC[65];
#pragma unroll 4
    for (int d = 65; d <= dmax; d++) {
        float2 xA = wA, xB = wB, xC = wC;
        wA = sA[d + 1];                       // prefetch next (pad covers d=dmax)
        wB = sB[d + 1];
        wC = sC[d + 1];

        float pm1 = __shfl_up_sync(0xffffffffu, aB, 1);
        float seA = (lane == 0) ? NEGV : xA.y;

        float nA = ladd2(aA + xA.x, pm1 + seA);
        float nB = ladd2(aB + xB.x, aA + xB.y);
        aC       = ladd2(aC + xC.x, aB + xC.y);   // uses old aB (sequenced)
        aA = nA;
        aB = nB;
    }

    // Loop stopped at d == dmax: owning lane's register IS alpha[tl][yl].
    float ll = 0.f; bool hit = false;
    if (uA == yl)                    { ll = aA; hit = true; }
    else if (uB == yl)               { ll = aB; hit = true; }
    else if (lane == 31 && yl == 64) { ll = aC; hit = true; }
    if (hit) g_ll[b] = ll + __ldg(g_blast + b * U1 + yl);
    __syncwarp();
    __threadfence();

    if (lane == 0) {
        int ticket = atomicAdd(&g_done, 1);
        if (ticket == B - 1) {                // last block: reduce + reset
            __threadfence();
            float sum = 0.f;
#pragma unroll
            for (int i = 0; i < B; i++) sum += g_ll[i];
            out[0] = -sum * (LN2 / B);        // back to natural log, mean
            g_done = 0;                       // deterministic across replays
        }
    }
}

// ---------------------------------------------------------------------------
extern "C" void kernel_launch(void* const* d_in, const int* in_sizes, int n_in,
                              void* d_out, int out_size)
{
    const float* logits = (const float*)d_in[0];
    const int*   labels = (const int*)  d_in[1];
    const int*   f_len  = (const int*)  d_in[2];
    const int*   y_len  = (const int*)  d_in[3];

    int rows = B * T * U1;                    // 133,120 warps
    int blocks = (rows * 32 + 255) / 256;
    softmax_kernel<<<blocks, 256>>>(logits, labels, f_len, y_len);

    size_t smem = (size_t)(PKSZ + PKPAD) * sizeof(float2);   // 133,184 B
    cudaFuncSetAttribute(alpha_kernel,
                         cudaFuncAttributeMaxDynamicSharedMemorySize, (int)smem);
    alpha_kernel<<<B, 256, smem>>>(f_len, y_len, (float*)d_out);
}

// round 12
// speedup vs baseline: 4.1530x; 1.0383x over previous
#include <cuda_runtime.h>
#include <cuda_bf16.h>

constexpr int B  = 8;
constexpr int T  = 256;
constexpr int U  = 64;
constexpr int U1 = U + 1;   // 65
constexpr int V  = 1024;
constexpr int PKROW = 256;                // pk row stride (t dimension)
constexpr int PKSZ  = U1 * PKROW;         // 16640 float2 per batch
constexpr int PKPAD = 8;                  // guard

#define INV_LN2 1.4426950408889634f
#define LN2     0.6931471805599453f
#define FULL    0xffffffffu

// Scratch (allocation-free rule: __device__ globals).
// Packed LINEAR-domain operands: pk[b][u][t] = (P_blank[u][t-1], P_emit[u-1][t]).
// Cell u at diagonal d (t = d-u) reads exactly pk[u][t] -> one LDS.64.
__device__ float2 g_pack[B * PKSZ];
__device__ float  g_blast[B * U1];        // log2 blank[u][t_last] for final add
__device__ float  g_ll[B];                // log2-domain per-batch ll
__device__ int    g_done;                 // ticket: last alpha block reduces

// ---------------------------------------------------------------------------
// Kernel 1: one warp per (b,t,u) row of V=1024. Register-resident row
// (8 x float4 per lane), warp max + warp sum-exp. HBM-bound: 545 MB read.
// Writes linear-domain probabilities for the alpha recurrence.
// ---------------------------------------------------------------------------
__global__ void __launch_bounds__(256) softmax_kernel(
    const float* __restrict__ logits,
    const int*   __restrict__ labels,
    const int*   __restrict__ f_len,
    const int*   __restrict__ y_len)
{
    int gw   = (blockIdx.x * blockDim.x + threadIdx.x) >> 5;   // global warp = row
    int lane = threadIdx.x & 31;
    if (gw >= B * T * U1) return;

    const float4* row = reinterpret_cast<const float4*>(logits) + (size_t)gw * (V / 4);

    float4 v[8];
    float mx = -3.4e38f;
#pragma unroll
    for (int k = 0; k < 8; k++) {
        v[k] = row[k * 32 + lane];                       // coalesced 128B/warp
        mx = fmaxf(mx, fmaxf(fmaxf(v[k].x, v[k].y), fmaxf(v[k].z, v[k].w)));
    }
#pragma unroll
    for (int o = 16; o; o >>= 1) mx = fmaxf(mx, __shfl_xor_sync(FULL, mx, o));

    float s = 0.f;
#pragma unroll
    for (int k = 0; k < 8; k++) {
        s += __expf(v[k].x - mx) + __expf(v[k].y - mx)
           + __expf(v[k].z - mx) + __expf(v[k].w - mx);
    }
#pragma unroll
    for (int o = 16; o; o >>= 1) s += __shfl_xor_sync(FULL, s, o);

    float lse = mx + __logf(s);

    if (lane == 0) {
        int b = gw / (T * U1);
        int r = gw % (T * U1);
        int t = r / U1;
        int u = r % U1;
        float* pk = reinterpret_cast<float*>(g_pack + b * PKSZ);
        float bl_lp = v[0].x - lse;                      // log blank
        float bl_p  = __expf(bl_lp);                     // linear blank prob
        if (t + 1 < PKROW) pk[(u * PKROW + t + 1) * 2 + 0] = bl_p;   // .x slot
        if (t == f_len[b] - 1) g_blast[b * U1 + u] = bl_lp * INV_LN2;
        if (u < U) {
            float e = 0.f;                               // masked emit: prob 0
            if (u < y_len[b]) {
                int l = labels[b * U + u];
                e = __expf(__ldg(logits + (size_t)gw * V + l) - lse);  // L1 hit
            }
            pk[((u + 1) * PKROW + t) * 2 + 1] = e;       // .y slot
        }
    }
}

// ---------------------------------------------------------------------------
// Kernel 2: alpha recurrence, one block per batch, LINEAR domain with
// PER-LANE exponent frames. Lane l owns u = {2l, 2l+1}; all lanes compute
// u = 64 (only lane 31's is real).
//   a[u] <- a[u]*P_blank + (neighbor a[u-1])*P_emit*2^(Ef_l - Ef_{l-1})
// Each lane rescales its own registers (exact 2^k) every 8 diagonals keyed
// on its own aA; Ef accumulates so log2(alpha) = log2(reg) - Ef.
// Injection at d==u anchors the frame (aA = 2^44, Ef = 44 - a0[u]).
// Pre-injection and dead (u > y_len) cells remain exactly 0 (sc gating).
// ---------------------------------------------------------------------------
extern __shared__ float2 shpk[];           // [PKSZ + PKPAD]

__global__ void __launch_bounds__(256) alpha_kernel(
    const int* __restrict__ f_len,
    const int* __restrict__ y_len,
    float*     __restrict__ out)
{
    int b   = blockIdx.x;
    int tid = threadIdx.x;

    {   // Stage packed operands into smem (coalesced float4, from hot L2).
        const float4* src = reinterpret_cast<const float4*>(g_pack + b * PKSZ);
        float4*       dst = reinterpret_cast<float4*>(shpk);
        for (int i = tid; i < PKSZ / 2; i += 256) dst[i] = src[i];
    }
    __syncthreads();
    if (tid >= 32) return;

    int lane = tid;
    int tl = __ldg(f_len + b) - 1;         // last valid frame (127..255)
    int yl = __ldg(y_len + b);             // label length    (32..64)
    const int dmax = tl + yl;              // in [159, 319]

    const int uA = 2 * lane, uB = 2 * lane + 1;
    // Stream for cell u, indexed by diagonal d: shpk[u*(PKROW-1) + d]
    const float2* sA = shpk + uA * (PKROW - 1);
    const float2* sB = shpk + uB * (PKROW - 1);
    const float2* sC = shpk + 64 * (PKROW - 1);     // same addr all lanes: bcast

    // a0[u] = log2 exclusive cumsum of emit[0][*]  (emit[0][u] = pk[u+1][0].y)
    float e0A = __log2f(shpk[(uA + 1) * PKROW].y);  // log2f(0) = -inf OK
    float e0B = __log2f(shpk[(uB + 1) * PKROW].y);
    float S = e0A + e0B;
#pragma unroll
    for (int o = 1; o < 32; o <<= 1) {
        float tv = __shfl_up_sync(FULL, S, o);
        if (lane >= o) S += tv;
    }
    float Sx = __shfl_up_sync(FULL, S, 1);
    if (lane == 0) Sx = 0.f;
    float a0A = Sx;
    float a0B = Sx + e0A;
    float a0C = __shfl_sync(FULL, S, 31);
    const bool validA = (a0A > -1e29f);

    const float SC44 = __int_as_float((44 + 127) << 23);   // 2^44 exactly

    float aA = 0.f, aB = 0.f, aC = 0.f;    // linear, per-lane frame
    float Ef = 0.f;                        // log2 alpha = log2(reg) - Ef
    float cA = 1.f, cB = 1.f, cC = 1.f, cE = 0.f;   // capture at d == dmax

    // Per-lane exact power-of-2 rescale keyed on own aA.
    auto RESCALE = [&]() {
        int bits = __float_as_int(aA);
        int ex = (bits >> 23) & 0xff;
        int k = 171 - ex;                             // bring aA to ~2^44
        if (!(aA > 0.f) || ex == 255) k = 0;
        k = max(-126, min(126, k));
        float s2 = __int_as_float((k + 127) << 23);   // 2^k exactly
        aA *= s2; aB *= s2; aC *= s2; Ef += (float)k;
    };

    // ---- ramp: d in [0, 64]; sc refreshed per step (Ef moves at injections)
#pragma unroll 4
    for (int d = 0; d <= 64; d++) {
        if ((d & 7) == 0) RESCALE();
        float Efm1 = __shfl_up_sync(FULL, Ef, 1);
        float sc   = exp2f(Ef - Efm1);
        float pm1  = __shfl_up_sync(FULL, aB, 1);
        float2 wA = sA[d], wB = sB[d], wC = sC[d];
        float emA_s = (lane == 0) ? 0.f : wA.y * sc;
        float nA = fmaf(pm1, emA_s, aA * wA.x);
        float nB = fmaf(aA, wB.y, aB * wB.x);
        float nC = fmaf(aB, wC.y, aC * wC.x);
        if (d == uA) {                     // anchor frame at first own cell
            nA = validA ? SC44 : 0.f;
            Ef = validA ? (44.f - a0A) : -3000.f;
        }
        if (d == uB) nB = exp2f(a0B + Ef);   // -inf a0B -> exact 0
        if (d == 64) nC = exp2f(a0C + Ef);
        aA = nA; aB = nB; aC = nC;
    }

    // ---- steady: d in [65, 319]; sc per 8-block; capture at d == dmax ----
    auto STEP = [&](int d, float sc) {
        float pm1 = __shfl_up_sync(FULL, aB, 1);
        float2 wA = sA[d], wB = sB[d], wC = sC[d];
        float emA_s = (lane == 0) ? 0.f : wA.y * sc;
        float nA = fmaf(pm1, emA_s, aA * wA.x);
        float nB = fmaf(aA, wB.y, aB * wB.x);
        float nC = fmaf(aB, wC.y, aC * wC.x);
        aA = nA; aB = nB; aC = nC;
        if (d == dmax) { cA = aA; cB = aB; cC = aC; cE = Ef; }
    };

#pragma unroll 1
    for (int base = 65; base < 313; base += 8) {
        RESCALE();
        float Efm1 = __shfl_up_sync(FULL, Ef, 1);
        float sc   = exp2f(Ef - Efm1);
#pragma unroll
        for (int s = 0; s < 8; s++) STEP(base + s, sc);
    }
    {
        RESCALE();
        float Efm1 = __shfl_up_sync(FULL, Ef, 1);
        float sc   = exp2f(Ef - Efm1);
#pragma unroll
        for (int d = 313; d <= 319; d++) STEP(d, sc);
    }

    // Owner lane's captured register IS alpha[tl][yl] (frame cE).
    float reg = (uA == yl) ? cA : ((uB == yl) ? cB : cC);
    bool hit = (uA == yl) || (uB == yl) || (lane == 31 && yl == 64);
    if (hit) g_ll[b] = (__log2f(reg) - cE) + __ldg(g_blast + b * U1 + yl);
    __syncwarp();
    __threadfence();

    if (lane == 0) {
        int ticket = atomicAdd(&g_done, 1);
        if (ticket == B - 1) {             // last block: reduce + reset
            __threadfence();
            float sum = 0.f;
#pragma unroll
            for (int i = 0; i < B; i++) sum += g_ll[i];
            out[0] = -sum * (LN2 / B);     // back to natural log, mean
            g_done = 0;                    // deterministic across replays
        }
    }
}

// ---------------------------------------------------------------------------
extern "C" void kernel_launch(void* const* d_in, const int* in_sizes, int n_in,
                              void* d_out, int out_size)
{
    const float* logits = (const float*)d_in[0];
    const int*   labels = (const int*)  d_in[1];
    const int*   f_len  = (const int*)  d_in[2];
    const int*   y_len  = (const int*)  d_in[3];

    int rows = B * T * U1;                    // 133,120 warps
    int blocks = (rows * 32 + 255) / 256;
    softmax_kernel<<<blocks, 256>>>(logits, labels, f_len, y_len);

    size_t smem = (size_t)(PKSZ + PKPAD) * sizeof(float2);   // 133,184 B
    cudaFuncSetAttribute(alpha_kernel,
                         cudaFuncAttributeMaxDynamicSharedMemorySize, (int)smem);
    alpha_kernel<<<B, 256, smem>>>(f_len, y_len, (float*)d_out);
}